// round 13
// baseline (speedup 1.0000x reference)
#include <cuda_runtime.h>

#define N_AG 512
#define T_STEPS 12
#define NB 128
#define NT 512
#define ROWSTRIDE 68                        // floats per staged B row (64 + 4 pad)
#define DYN_SMEM (N_AG * ROWSTRIDE * 4)     // 139264 bytes: all 512 B rows
#define NEG_INF __int_as_float(0xff800000)

// ------------------------- cross-block scratch -------------------------
__device__ float g_Brow[2][N_AG * 64];     // [buf][j*64 + d] row-major B
__device__ unsigned g_cnt[T_STEPS];
__device__ volatile unsigned g_flag[T_STEPS];
__device__ unsigned g_depart;

__device__ __forceinline__ float sigf(float x) { return 1.f / (1.f + __expf(-x)); }

__device__ __forceinline__ unsigned cvt_tf32(float x) {
    unsigned u;
    asm("cvt.rna.tf32.f32 %0, %1;" : "=r"(u) : "f"(x));
    return u;
}
__device__ __forceinline__ void mma_tf32(
    float& d0, float& d1, float& d2, float& d3,
    unsigned a0, unsigned a1, unsigned a2, unsigned a3,
    unsigned b0, unsigned b1)
{
    asm volatile(
        "mma.sync.aligned.m16n8k8.row.col.f32.tf32.tf32.f32 "
        "{%0,%1,%2,%3}, {%4,%5,%6,%7}, {%8,%9}, {%0,%1,%2,%3};"
        : "+f"(d0), "+f"(d1), "+f"(d2), "+f"(d3)
        : "r"(a0), "r"(a1), "r"(a2), "r"(a3), "r"(b0), "r"(b1));
}

__global__ __launch_bounds__(NT, 1) void k_fused(
    const float* __restrict__ p, const float* __restrict__ c, const float* __restrict__ z,
    const float* __restrict__ obs, const float* __restrict__ eps, const float* __restrict__ c0,
    const int* __restrict__ nei,
    const float* __restrict__ W_in, const float* __restrict__ b_in,
    const float* __restrict__ W_ih, const float* __restrict__ W_hh,
    const float* __restrict__ b_ih, const float* __restrict__ b_hh,
    const float* __restrict__ W_m, const float* __restrict__ b_m,
    const float* __restrict__ W_v, const float* __restrict__ b_v,
    const float* __restrict__ W_zh, const float* __restrict__ b_zh,
    const float* __restrict__ W_se, const float* __restrict__ b_se,
    const float* __restrict__ W1, const float* __restrict__ b1,
    const float* __restrict__ W2, const float* __restrict__ b2,
    float* __restrict__ out)
{
    extern __shared__ float smB[];                // [512 rows][ROWSTRIDE]

    __shared__ __align__(16) float AshF[4][64];   // A[i][d] per agent
    __shared__ float  sh_Mse0[64];
    __shared__ float  sh_Mse1[64];
    __shared__ float  sh_b1[64];
    __shared__ float  sh_b2[8];
    __shared__ float  sh_h[4][8], sh_cl[4][8];
    __shared__ float2 sh_pos[4], sh_prev[4];
    __shared__ float  red[16][8];                 // raw per-warp maxes (may be -inf)
    __shared__ int    neis[4][N_AG];              // prefetched nei rows, this block's agents

    const int tid  = threadIdx.x;
    const int warp = tid >> 5;
    const int lane = tid & 31;
    const int blk  = blockIdx.x;
    const int g    = lane >> 2;     // mma groupID
    const int tg   = lane & 3;      // mma threadID_in_group

    // ---------------- W2 fragments (constants, registers for whole kernel) ----------------
    // b0(ks) = W2[8ks+tg][g], b1(ks) = W2[8ks+tg+4][g]
    unsigned w2f[16];
#pragma unroll
    for (int ks = 0; ks < 8; ks++) {
        w2f[2 * ks]     = cvt_tf32(W2[(8 * ks + tg) * 8 + g]);
        w2f[2 * ks + 1] = cvt_tf32(W2[(8 * ks + tg + 4) * 8 + g]);
    }

    // ---------------- preload constants ----------------
    if (tid < 64) {
        int d = tid;
        float m0 = 0.f, m1 = 0.f, bb = b1[d];
        for (int u = 0; u < 32; u++) {
            float w = W1[u * 64 + d];
            m0 += W_se[u] * w;
            m1 += W_se[32 + u] * w;
            bb += b_se[u] * w;
        }
        sh_Mse0[d] = m0; sh_Mse1[d] = m1; sh_b1[d] = bb;
    } else if (tid < 72) {
        sh_b2[tid - 64] = b2[tid - 64];
    }

    // ---------------- init per-agent state (warps 0..3) ----------------
    if (warp < 4) {
        int i = blk * 4 + warp;
        if (lane < 8) {
            float z0 = z[2 * i], z1 = z[2 * i + 1];
            sh_h[warp][lane]  = z0 * W_zh[lane] + z1 * W_zh[8 + lane] + b_zh[lane];
            sh_cl[warp][lane] = c0[i * 8 + lane];
        }
        if (lane == 0) {
            sh_pos[warp]  = make_float2(obs[(7 * N_AG + i) * 2], obs[(7 * N_AG + i) * 2 + 1]);
            sh_prev[warp] = make_float2(p[2 * i], p[2 * i + 1]);
        }
    }
    __syncthreads();

    for (int t = 0; t <= T_STEPS; t++) {
        // ========= step phase (warps 0-3) || nei prefetch (warps 4-7) =========
        if (warp < 4) {
            int a = warp;
            int i = blk * 4 + a;

            // ctx from raw pooled maxes; fold +b2 and relu here (exact)
            float ctxl = 0.f;
            if (t >= 1 && lane < 8) {
                float v = fmaxf(fmaxf(red[a * 4 + 0][lane], red[a * 4 + 1][lane]),
                                fmaxf(red[a * 4 + 2][lane], red[a * 4 + 3][lane]));
                ctxl = fmaxf(v + sh_b2[lane], 0.f);   // -inf -> 0 (no neighbors)
            }
            float ctx[8];
#pragma unroll
            for (int u = 0; u < 8; u++) ctx[u] = __shfl_sync(0xffffffffu, ctxl, u);

            float h[8];
#pragma unroll
            for (int u = 0; u < 8; u++) h[u] = sh_h[a][u];
            float cl8 = sh_cl[a][lane & 7];

            float pos0, pos1, pv0, pv1;
            if (t > 0) {
                int tc = t - 1;
                float mu[2], lv[2];
#pragma unroll
                for (int m = 0; m < 2; m++) {
                    float s  = b_m[m];
                    float s2 = b_v[m];
#pragma unroll
                    for (int u = 0; u < 4; u++) {
                        s  += h[u]     * W_m[u * 2 + m];
                        s2 += h[4 + u] * W_v[u * 2 + m];
                    }
#pragma unroll
                    for (int k = 0; k < 8; k++) {
                        s  += ctx[k] * W_m[(4 + k) * 2 + m];
                        s2 += ctx[k] * W_v[(4 + k) * 2 + m];
                    }
                    mu[m] = s; lv[m] = s2;
                }
                float e0 = eps[(tc * N_AG + i) * 2];
                float e1 = eps[(tc * N_AG + i) * 2 + 1];
                float p0 = mu[0] + e0 * expf(0.5f * lv[0]);
                float p1 = mu[1] + e1 * expf(0.5f * lv[1]);
                pv0 = p0; pv1 = p1;
                pos0 = sh_pos[a].x + p0;
                pos1 = sh_pos[a].y + p1;
                if (lane == 0) {
                    out[tc * 1024 + 2 * i]             = p0;
                    out[tc * 1024 + 2 * i + 1]         = p1;
                    out[12288 + tc * 1024 + 2 * i]     = mu[0];
                    out[12288 + tc * 1024 + 2 * i + 1] = mu[1];
                    out[24576 + tc * 1024 + 2 * i]     = lv[0];
                    out[24576 + tc * 1024 + 2 * i + 1] = lv[1];
                    sh_prev[a] = make_float2(pv0, pv1);
                    sh_pos[a]  = make_float2(pos0, pos1);
                }
            } else {
                pv0 = sh_prev[a].x; pv1 = sh_prev[a].y;
                pos0 = sh_pos[a].x; pos1 = sh_pos[a].y;
            }

            if (t < T_STEPS) {
                float x[20];
#pragma unroll
                for (int u = 0; u < 8; u++) x[u] = ctx[u];
                x[8] = pv0; x[9] = pv1;
#pragma unroll
                for (int u = 0; u < 8; u++) x[10 + u] = c[i * 8 + u];
                x[18] = z[2 * i]; x[19] = z[2 * i + 1];

                float xr = 0.f;
                if (lane < 16) {
                    float s = b_in[lane];
#pragma unroll
                    for (int v = 0; v < 20; v++) s += x[v] * W_in[v * 16 + lane];
                    xr = fmaxf(s, 0.f);
                }

                float gg2 = b_ih[lane] + b_hh[lane];
#pragma unroll
                for (int u = 0; u < 16; u++) {
                    float xu = __shfl_sync(0xffffffffu, xr, u);
                    gg2 += xu * W_ih[u * 32 + lane];
                }
#pragma unroll
                for (int u = 0; u < 8; u++) gg2 += h[u] * W_hh[u * 32 + lane];

                int u8 = lane & 7;
                float gi = __shfl_sync(0xffffffffu, gg2, u8);
                float gf = __shfl_sync(0xffffffffu, gg2, u8 + 8);
                float gG = __shfl_sync(0xffffffffu, gg2, u8 + 16);
                float go = __shfl_sync(0xffffffffu, gg2, u8 + 24);
                float cln = sigf(gf) * cl8 + sigf(gi) * tanhf(gG);
                float hn  = sigf(go) * tanhf(cln);
                if (lane < 8) {
                    sh_cl[a][lane] = cln;
                    sh_h[a][lane]  = hn;
                }
                float hw[8];
#pragma unroll
                for (int u = 0; u < 8; u++) hw[u] = __shfl_sync(0xffffffffu, hn, u);

                // A/B precompute: lane owns d-pair (2l, 2l+1)
                int d = 2 * lane;
                float m0x = sh_Mse0[d],  m0y = sh_Mse0[d + 1];
                float m1x = sh_Mse1[d],  m1y = sh_Mse1[d + 1];
                float bx = pos0 * m0x + pos1 * m1x;
                float by = pos0 * m0y + pos1 * m1y;
                float Ax = sh_b1[d] + bx,     Ay = sh_b1[d + 1] + by;
                float Bx = -bx,               By = -by;
#pragma unroll
                for (int u = 0; u < 8; u++) {
                    float2 wA = *(const float2*)(W1 + (40 + u) * 64 + d);
                    float2 wB = *(const float2*)(W1 + (32 + u) * 64 + d);
                    Ax = fmaf(hw[u], wA.x, Ax); Ay = fmaf(hw[u], wA.y, Ay);
                    Bx = fmaf(hw[u], wB.x, Bx); By = fmaf(hw[u], wB.y, By);
                }
                AshF[a][d]     = Ax;
                AshF[a][d + 1] = Ay;
                *(float2*)&g_Brow[t & 1][i * 64 + d] = make_float2(Bx, By);
            }
        } else if (warp < 8 && t < T_STEPS) {
            // ---- prefetch nei rows for this block's 4 agents ----
            int a = warp - 4;
            int i = blk * 4 + a;
            const int4* src = (const int4*)(nei + ((long)t * N_AG + i) * N_AG);
#pragma unroll
            for (int q = 0; q < 4; q++)
                *(int4*)&neis[a][(q * 32 + lane) * 4] = src[q * 32 + lane];
        }
        if (t == T_STEPS) break;
        __threadfence();
        __syncthreads();    // B rows / nei written, red consumed

        // ================= grid barrier t =================
        if (tid == 0) {
            unsigned v = atomicAdd(&g_cnt[t], 1u);
            if (v == NB - 1) {
                if (t > 0) { g_cnt[t - 1] = 0; g_flag[t - 1] = 0; }
                g_flag[t] = 1;
                __threadfence();
            } else {
                while (g_flag[t] == 0) { }
            }
            __threadfence();
        }
        __syncthreads();

        // ---- stage all 512 B rows into padded smem (coalesced) ----
        {
            const float4* src = (const float4*)g_Brow[t & 1];   // 8192 float4
#pragma unroll
            for (int it = 0; it < 16; it++) {
                int idx = it * NT + tid;
                int j = idx >> 4, c4 = idx & 15;
                *(float4*)&smB[j * ROWSTRIDE + c4 * 4] = src[idx];
            }
        }
        __syncthreads();

        // ========= pool phase: tf32 mma, warp = (agent, quarter) =========
        {
            int a  = warp >> 2;
            int q  = warp & 3;

            float m0 = NEG_INF, m1 = NEG_INF;   // cols 2tg, 2tg+1

#pragma unroll
            for (int rt = 0; rt < 8; rt++) {
                int j0 = q * 128 + rt * 16;
                int jA = j0 + g, jB = j0 + g + 8;
                const float* rowA = &smB[jA * ROWSTRIDE];
                const float* rowB = &smB[jB * ROWSTRIDE];

                float d0 = 0.f, d1 = 0.f, d2 = 0.f, d3 = 0.f;
#pragma unroll
                for (int ks = 0; ks < 8; ks++) {
                    int c1 = ks * 8 + tg, c2 = c1 + 4;
                    float a0f = fmaxf(AshF[a][c1] + rowA[c1], 0.f);
                    float a1f = fmaxf(AshF[a][c1] + rowB[c1], 0.f);
                    float a2f = fmaxf(AshF[a][c2] + rowA[c2], 0.f);
                    float a3f = fmaxf(AshF[a][c2] + rowB[c2], 0.f);
                    mma_tf32(d0, d1, d2, d3,
                             cvt_tf32(a0f), cvt_tf32(a1f), cvt_tf32(a2f), cvt_tf32(a3f),
                             w2f[2 * ks], w2f[2 * ks + 1]);
                }
                // D: d0=[jA][2tg], d1=[jA][2tg+1], d2=[jB][2tg], d3=[jB][2tg+1]
                if (neis[a][jA] > 0) { m0 = fmaxf(m0, d0); m1 = fmaxf(m1, d1); }
                if (neis[a][jB] > 0) { m0 = fmaxf(m0, d2); m1 = fmaxf(m1, d3); }
            }

            // reduce over g (lanes differing in bits 2..4)
#pragma unroll
            for (int off = 4; off <= 16; off <<= 1) {
                m0 = fmaxf(m0, __shfl_xor_sync(0xffffffffu, m0, off));
                m1 = fmaxf(m1, __shfl_xor_sync(0xffffffffu, m1, off));
            }
            if (lane < 4) {
                red[warp][2 * tg]     = m0;
                red[warp][2 * tg + 1] = m1;
            }
        }
        __syncthreads();    // red ready; smB reusable next step
    }

    // ---------------- replay-safe cleanup of last barrier ----------------
    if (tid == 0) {
        __threadfence();
        unsigned d = atomicAdd(&g_depart, 1u);
        if (d == NB - 1) {
            g_cnt[T_STEPS - 1] = 0;
            g_flag[T_STEPS - 1] = 0;
            g_depart = 0;
            __threadfence();
        }
    }
}

// ------------------------- launch -------------------------
extern "C" void kernel_launch(void* const* d_in, const int* in_sizes, int n_in,
                              void* d_out, int out_size)
{
    const float* p    = (const float*)d_in[0];
    const float* c    = (const float*)d_in[1];
    const float* z    = (const float*)d_in[2];
    const float* obs  = (const float*)d_in[3];
    const float* eps  = (const float*)d_in[4];
    const float* c0   = (const float*)d_in[5];
    const int*   nei  = (const int*)d_in[6];
    const float* W_in = (const float*)d_in[8];
    const float* b_in = (const float*)d_in[9];
    const float* W_ih = (const float*)d_in[10];
    const float* W_hh = (const float*)d_in[11];
    const float* b_ih = (const float*)d_in[12];
    const float* b_hh = (const float*)d_in[13];
    const float* W_m  = (const float*)d_in[14];
    const float* b_m  = (const float*)d_in[15];
    const float* W_v  = (const float*)d_in[16];
    const float* b_v  = (const float*)d_in[17];
    const float* W_zh = (const float*)d_in[18];
    const float* b_zh = (const float*)d_in[19];
    const float* W_se = (const float*)d_in[20];
    const float* b_se = (const float*)d_in[21];
    const float* W1   = (const float*)d_in[22];
    const float* b1   = (const float*)d_in[23];
    const float* W2   = (const float*)d_in[24];
    const float* b2   = (const float*)d_in[25];
    float* out = (float*)d_out;

    cudaFuncSetAttribute(k_fused, cudaFuncAttributeMaxDynamicSharedMemorySize, DYN_SMEM);
    k_fused<<<NB, NT, DYN_SMEM>>>(p, c, z, obs, eps, c0, nei,
                                  W_in, b_in, W_ih, W_hh, b_ih, b_hh,
                                  W_m, b_m, W_v, b_v, W_zh, b_zh,
                                  W_se, b_se, W1, b1, W2, b2, out);
}

// round 14
// speedup vs baseline: 1.0013x; 1.0013x over previous
#include <cuda_runtime.h>

#define N_AG 512
#define T_STEPS 12
#define NB 128
#define NT 512
#define ROWSTRIDE 68                        // floats per staged B row (64 + 4 pad)
#define DYN_SMEM (N_AG * ROWSTRIDE * 4)     // 139264 bytes: all 512 B rows
#define NEG_INF __int_as_float(0xff800000)

// ------------------------- cross-block scratch -------------------------
__device__ float g_Brow[2][N_AG * 64];     // [buf][j*64 + d] row-major B
__device__ unsigned g_cnt[T_STEPS];
__device__ volatile unsigned g_flag[T_STEPS];
__device__ unsigned g_depart;

__device__ __forceinline__ float sigf(float x) { return 1.f / (1.f + __expf(-x)); }

__device__ __forceinline__ unsigned cvt_tf32(float x) {
    unsigned u;
    asm("cvt.rna.tf32.f32 %0, %1;" : "=r"(u) : "f"(x));
    return u;
}
__device__ __forceinline__ void mma_tf32(
    float& d0, float& d1, float& d2, float& d3,
    unsigned a0, unsigned a1, unsigned a2, unsigned a3,
    unsigned b0, unsigned b1)
{
    asm volatile(
        "mma.sync.aligned.m16n8k8.row.col.f32.tf32.tf32.f32 "
        "{%0,%1,%2,%3}, {%4,%5,%6,%7}, {%8,%9}, {%0,%1,%2,%3};"
        : "+f"(d0), "+f"(d1), "+f"(d2), "+f"(d3)
        : "r"(a0), "r"(a1), "r"(a2), "r"(a3), "r"(b0), "r"(b1));
}

__global__ __launch_bounds__(NT, 1) void k_fused(
    const float* __restrict__ p, const float* __restrict__ c, const float* __restrict__ z,
    const float* __restrict__ obs, const float* __restrict__ eps, const float* __restrict__ c0,
    const int* __restrict__ nei,
    const float* __restrict__ W_in, const float* __restrict__ b_in,
    const float* __restrict__ W_ih, const float* __restrict__ W_hh,
    const float* __restrict__ b_ih, const float* __restrict__ b_hh,
    const float* __restrict__ W_m, const float* __restrict__ b_m,
    const float* __restrict__ W_v, const float* __restrict__ b_v,
    const float* __restrict__ W_zh, const float* __restrict__ b_zh,
    const float* __restrict__ W_se, const float* __restrict__ b_se,
    const float* __restrict__ W1, const float* __restrict__ b1,
    const float* __restrict__ W2, const float* __restrict__ b2,
    float* __restrict__ out)
{
    extern __shared__ float smB[];                // [512 rows][ROWSTRIDE]

    __shared__ __align__(16) float AshF[4][64];   // A[i][d] per agent
    __shared__ float  sh_Mse0[64];
    __shared__ float  sh_Mse1[64];
    __shared__ float  sh_b1[64];
    __shared__ float  sh_b2[8];
    __shared__ float  sh_h[4][8], sh_cl[4][8];
    __shared__ float2 sh_pos[4], sh_prev[4];
    __shared__ float  red[16][8];                 // raw per-warp maxes (may be -inf)
    __shared__ int    neis[4][N_AG];              // prefetched nei rows, this block's agents

    const int tid  = threadIdx.x;
    const int warp = tid >> 5;
    const int lane = tid & 31;
    const int blk  = blockIdx.x;
    const int g    = lane >> 2;     // mma groupID
    const int tg   = lane & 3;      // mma threadID_in_group

    // ---------------- W2 fragments (constants, registers for whole kernel) ----------------
    // b0(ks) = W2[8ks+tg][g], b1(ks) = W2[8ks+tg+4][g]
    unsigned w2f[16];
#pragma unroll
    for (int ks = 0; ks < 8; ks++) {
        w2f[2 * ks]     = cvt_tf32(W2[(8 * ks + tg) * 8 + g]);
        w2f[2 * ks + 1] = cvt_tf32(W2[(8 * ks + tg + 4) * 8 + g]);
    }

    // ---------------- preload constants ----------------
    if (tid < 64) {
        int d = tid;
        float m0 = 0.f, m1 = 0.f, bb = b1[d];
        for (int u = 0; u < 32; u++) {
            float w = W1[u * 64 + d];
            m0 += W_se[u] * w;
            m1 += W_se[32 + u] * w;
            bb += b_se[u] * w;
        }
        sh_Mse0[d] = m0; sh_Mse1[d] = m1; sh_b1[d] = bb;
    } else if (tid < 72) {
        sh_b2[tid - 64] = b2[tid - 64];
    }

    // ---------------- init per-agent state (warps 0..3) ----------------
    if (warp < 4) {
        int i = blk * 4 + warp;
        if (lane < 8) {
            float z0 = z[2 * i], z1 = z[2 * i + 1];
            sh_h[warp][lane]  = z0 * W_zh[lane] + z1 * W_zh[8 + lane] + b_zh[lane];
            sh_cl[warp][lane] = c0[i * 8 + lane];
        }
        if (lane == 0) {
            sh_pos[warp]  = make_float2(obs[(7 * N_AG + i) * 2], obs[(7 * N_AG + i) * 2 + 1]);
            sh_prev[warp] = make_float2(p[2 * i], p[2 * i + 1]);
        }
    }
    __syncthreads();

    for (int t = 0; t <= T_STEPS; t++) {
        // ========= step phase (warps 0-3) || nei prefetch (warps 4-7) =========
        if (warp < 4) {
            int a = warp;
            int i = blk * 4 + a;

            // ctx from raw pooled maxes; fold +b2 and relu here (exact)
            float ctxl = 0.f;
            if (t >= 1 && lane < 8) {
                float v = fmaxf(fmaxf(red[a * 4 + 0][lane], red[a * 4 + 1][lane]),
                                fmaxf(red[a * 4 + 2][lane], red[a * 4 + 3][lane]));
                ctxl = fmaxf(v + sh_b2[lane], 0.f);   // -inf -> 0 (no neighbors)
            }
            float ctx[8];
#pragma unroll
            for (int u = 0; u < 8; u++) ctx[u] = __shfl_sync(0xffffffffu, ctxl, u);

            float h[8];
#pragma unroll
            for (int u = 0; u < 8; u++) h[u] = sh_h[a][u];
            float cl8 = sh_cl[a][lane & 7];

            float pos0, pos1, pv0, pv1;
            if (t > 0) {
                int tc = t - 1;
                float mu[2], lv[2];
#pragma unroll
                for (int m = 0; m < 2; m++) {
                    float s  = b_m[m];
                    float s2 = b_v[m];
#pragma unroll
                    for (int u = 0; u < 4; u++) {
                        s  += h[u]     * W_m[u * 2 + m];
                        s2 += h[4 + u] * W_v[u * 2 + m];
                    }
#pragma unroll
                    for (int k = 0; k < 8; k++) {
                        s  += ctx[k] * W_m[(4 + k) * 2 + m];
                        s2 += ctx[k] * W_v[(4 + k) * 2 + m];
                    }
                    mu[m] = s; lv[m] = s2;
                }
                float e0 = eps[(tc * N_AG + i) * 2];
                float e1 = eps[(tc * N_AG + i) * 2 + 1];
                float p0 = mu[0] + e0 * expf(0.5f * lv[0]);
                float p1 = mu[1] + e1 * expf(0.5f * lv[1]);
                pv0 = p0; pv1 = p1;
                pos0 = sh_pos[a].x + p0;
                pos1 = sh_pos[a].y + p1;
                if (lane == 0) {
                    out[tc * 1024 + 2 * i]             = p0;
                    out[tc * 1024 + 2 * i + 1]         = p1;
                    out[12288 + tc * 1024 + 2 * i]     = mu[0];
                    out[12288 + tc * 1024 + 2 * i + 1] = mu[1];
                    out[24576 + tc * 1024 + 2 * i]     = lv[0];
                    out[24576 + tc * 1024 + 2 * i + 1] = lv[1];
                    sh_prev[a] = make_float2(pv0, pv1);
                    sh_pos[a]  = make_float2(pos0, pos1);
                }
            } else {
                pv0 = sh_prev[a].x; pv1 = sh_prev[a].y;
                pos0 = sh_pos[a].x; pos1 = sh_pos[a].y;
            }

            if (t < T_STEPS) {
                float x[20];
#pragma unroll
                for (int u = 0; u < 8; u++) x[u] = ctx[u];
                x[8] = pv0; x[9] = pv1;
#pragma unroll
                for (int u = 0; u < 8; u++) x[10 + u] = c[i * 8 + u];
                x[18] = z[2 * i]; x[19] = z[2 * i + 1];

                float xr = 0.f;
                if (lane < 16) {
                    float s = b_in[lane];
#pragma unroll
                    for (int v = 0; v < 20; v++) s += x[v] * W_in[v * 16 + lane];
                    xr = fmaxf(s, 0.f);
                }

                float gg2 = b_ih[lane] + b_hh[lane];
#pragma unroll
                for (int u = 0; u < 16; u++) {
                    float xu = __shfl_sync(0xffffffffu, xr, u);
                    gg2 += xu * W_ih[u * 32 + lane];
                }
#pragma unroll
                for (int u = 0; u < 8; u++) gg2 += h[u] * W_hh[u * 32 + lane];

                int u8 = lane & 7;
                float gi = __shfl_sync(0xffffffffu, gg2, u8);
                float gf = __shfl_sync(0xffffffffu, gg2, u8 + 8);
                float gG = __shfl_sync(0xffffffffu, gg2, u8 + 16);
                float go = __shfl_sync(0xffffffffu, gg2, u8 + 24);
                float cln = sigf(gf) * cl8 + sigf(gi) * tanhf(gG);
                float hn  = sigf(go) * tanhf(cln);
                if (lane < 8) {
                    sh_cl[a][lane] = cln;
                    sh_h[a][lane]  = hn;
                }
                float hw[8];
#pragma unroll
                for (int u = 0; u < 8; u++) hw[u] = __shfl_sync(0xffffffffu, hn, u);

                // A/B precompute: lane owns d-pair (2l, 2l+1)
                int d = 2 * lane;
                float m0x = sh_Mse0[d],  m0y = sh_Mse0[d + 1];
                float m1x = sh_Mse1[d],  m1y = sh_Mse1[d + 1];
                float bx = pos0 * m0x + pos1 * m1x;
                float by = pos0 * m0y + pos1 * m1y;
                float Ax = sh_b1[d] + bx,     Ay = sh_b1[d + 1] + by;
                float Bx = -bx,               By = -by;
#pragma unroll
                for (int u = 0; u < 8; u++) {
                    float2 wA = *(const float2*)(W1 + (40 + u) * 64 + d);
                    float2 wB = *(const float2*)(W1 + (32 + u) * 64 + d);
                    Ax = fmaf(hw[u], wA.x, Ax); Ay = fmaf(hw[u], wA.y, Ay);
                    Bx = fmaf(hw[u], wB.x, Bx); By = fmaf(hw[u], wB.y, By);
                }
                AshF[a][d]     = Ax;
                AshF[a][d + 1] = Ay;
                *(float2*)&g_Brow[t & 1][i * 64 + d] = make_float2(Bx, By);
            }
        } else if (warp < 8 && t < T_STEPS) {
            // ---- prefetch nei rows for this block's 4 agents ----
            int a = warp - 4;
            int i = blk * 4 + a;
            const int4* src = (const int4*)(nei + ((long)t * N_AG + i) * N_AG);
#pragma unroll
            for (int q = 0; q < 4; q++)
                *(int4*)&neis[a][(q * 32 + lane) * 4] = src[q * 32 + lane];
        }
        if (t == T_STEPS) break;
        __threadfence();
        __syncthreads();    // B rows / nei written, red consumed

        // ================= grid barrier t =================
        if (tid == 0) {
            unsigned v = atomicAdd(&g_cnt[t], 1u);
            if (v == NB - 1) {
                if (t > 0) { g_cnt[t - 1] = 0; g_flag[t - 1] = 0; }
                g_flag[t] = 1;
                __threadfence();
            } else {
                while (g_flag[t] == 0) { }
            }
            __threadfence();
        }
        __syncthreads();

        // ---- stage all 512 B rows into padded smem (coalesced) ----
        {
            const float4* src = (const float4*)g_Brow[t & 1];   // 8192 float4
#pragma unroll
            for (int it = 0; it < 16; it++) {
                int idx = it * NT + tid;
                int j = idx >> 4, c4 = idx & 15;
                *(float4*)&smB[j * ROWSTRIDE + c4 * 4] = src[idx];
            }
        }
        __syncthreads();

        // ========= pool phase: tf32 mma, warp = (agent, quarter) =========
        {
            int a  = warp >> 2;
            int q  = warp & 3;

            float m0 = NEG_INF, m1 = NEG_INF;   // cols 2tg, 2tg+1

#pragma unroll
            for (int rt = 0; rt < 8; rt++) {
                int j0 = q * 128 + rt * 16;
                int jA = j0 + g, jB = j0 + g + 8;
                const float* rowA = &smB[jA * ROWSTRIDE];
                const float* rowB = &smB[jB * ROWSTRIDE];

                float d0 = 0.f, d1 = 0.f, d2 = 0.f, d3 = 0.f;
#pragma unroll
                for (int ks = 0; ks < 8; ks++) {
                    int c1 = ks * 8 + tg, c2 = c1 + 4;
                    float a0f = fmaxf(AshF[a][c1] + rowA[c1], 0.f);
                    float a1f = fmaxf(AshF[a][c1] + rowB[c1], 0.f);
                    float a2f = fmaxf(AshF[a][c2] + rowA[c2], 0.f);
                    float a3f = fmaxf(AshF[a][c2] + rowB[c2], 0.f);
                    mma_tf32(d0, d1, d2, d3,
                             cvt_tf32(a0f), cvt_tf32(a1f), cvt_tf32(a2f), cvt_tf32(a3f),
                             w2f[2 * ks], w2f[2 * ks + 1]);
                }
                // D: d0=[jA][2tg], d1=[jA][2tg+1], d2=[jB][2tg], d3=[jB][2tg+1]
                if (neis[a][jA] > 0) { m0 = fmaxf(m0, d0); m1 = fmaxf(m1, d1); }
                if (neis[a][jB] > 0) { m0 = fmaxf(m0, d2); m1 = fmaxf(m1, d3); }
            }

            // reduce over g (lanes differing in bits 2..4)
#pragma unroll
            for (int off = 4; off <= 16; off <<= 1) {
                m0 = fmaxf(m0, __shfl_xor_sync(0xffffffffu, m0, off));
                m1 = fmaxf(m1, __shfl_xor_sync(0xffffffffu, m1, off));
            }
            if (lane < 4) {
                red[warp][2 * tg]     = m0;
                red[warp][2 * tg + 1] = m1;
            }
        }
        __syncthreads();    // red ready; smB reusable next step
    }

    // ---------------- replay-safe cleanup of last barrier ----------------
    if (tid == 0) {
        __threadfence();
        unsigned d = atomicAdd(&g_depart, 1u);
        if (d == NB - 1) {
            g_cnt[T_STEPS - 1] = 0;
            g_flag[T_STEPS - 1] = 0;
            g_depart = 0;
            __threadfence();
        }
    }
}

// ------------------------- launch -------------------------
extern "C" void kernel_launch(void* const* d_in, const int* in_sizes, int n_in,
                              void* d_out, int out_size)
{
    const float* p    = (const float*)d_in[0];
    const float* c    = (const float*)d_in[1];
    const float* z    = (const float*)d_in[2];
    const float* obs  = (const float*)d_in[3];
    const float* eps  = (const float*)d_in[4];
    const float* c0   = (const float*)d_in[5];
    const int*   nei  = (const int*)d_in[6];
    const float* W_in = (const float*)d_in[8];
    const float* b_in = (const float*)d_in[9];
    const float* W_ih = (const float*)d_in[10];
    const float* W_hh = (const float*)d_in[11];
    const float* b_ih = (const float*)d_in[12];
    const float* b_hh = (const float*)d_in[13];
    const float* W_m  = (const float*)d_in[14];
    const float* b_m  = (const float*)d_in[15];
    const float* W_v  = (const float*)d_in[16];
    const float* b_v  = (const float*)d_in[17];
    const float* W_zh = (const float*)d_in[18];
    const float* b_zh = (const float*)d_in[19];
    const float* W_se = (const float*)d_in[20];
    const float* b_se = (const float*)d_in[21];
    const float* W1   = (const float*)d_in[22];
    const float* b1   = (const float*)d_in[23];
    const float* W2   = (const float*)d_in[24];
    const float* b2   = (const float*)d_in[25];
    float* out = (float*)d_out;

    cudaFuncSetAttribute(k_fused, cudaFuncAttributeMaxDynamicSharedMemorySize, DYN_SMEM);
    k_fused<<<NB, NT, DYN_SMEM>>>(p, c, z, obs, eps, c0, nei,
                                  W_in, b_in, W_ih, W_hh, b_ih, b_hh,
                                  W_m, b_m, W_v, b_v, W_zh, b_zh,
                                  W_se, b_se, W1, b1, W2, b2, out);
}